// round 6
// baseline (speedup 1.0000x reference)
#include <cuda_runtime.h>
#include <cuda_bf16.h>

#define N_DIM 4096
#define B_DIM 8192

// Scratch for the extracted diagonal (allocation-free rule: __device__ global).
__device__ float g_diag[N_DIM];

__global__ void extract_diag_kernel(const float* __restrict__ weight) {
    int i = blockIdx.x * blockDim.x + threadIdx.x;
    if (i < N_DIM) {
        g_diag[i] = weight[(size_t)i * N_DIM + i];
    }
}

__global__ void __launch_bounds__(256)
scale_bias_kernel(const float4* __restrict__ in4,
                  const float4* __restrict__ bias4,
                  float4* __restrict__ out4) {
    const float4* __restrict__ diag4 = reinterpret_cast<const float4*>(g_diag);

    // Each thread handles 8 floats as TWO independent float4 loads,
    // front-batched for MLP=2. No cache-policy hints (R5 showed they regress).
    unsigned idx8 = blockIdx.x * blockDim.x + threadIdx.x;  // 0 .. 4194303
    unsigned i0   = idx8 * 2;                               // first float4 index
    unsigned col4 = i0 & (N_DIM / 4 - 1);                   // column in float4 units
                                                            // (col4+1 stays in-row: N/4=1024 even)

    // Front-batch the two big loads (independent → both in flight).
    float4 x0 = __ldg(&in4[i0 + 0]);
    float4 x1 = __ldg(&in4[i0 + 1]);

    float4 d0 = __ldg(&diag4[col4 + 0]);
    float4 d1 = __ldg(&diag4[col4 + 1]);
    float4 b0 = __ldg(&bias4[col4 + 0]);
    float4 b1 = __ldg(&bias4[col4 + 1]);

    float4 y0, y1;
    y0.x = fmaf(x0.x, d0.x, b0.x);
    y0.y = fmaf(x0.y, d0.y, b0.y);
    y0.z = fmaf(x0.z, d0.z, b0.z);
    y0.w = fmaf(x0.w, d0.w, b0.w);
    y1.x = fmaf(x1.x, d1.x, b1.x);
    y1.y = fmaf(x1.y, d1.y, b1.y);
    y1.z = fmaf(x1.z, d1.z, b1.z);
    y1.w = fmaf(x1.w, d1.w, b1.w);

    out4[i0 + 0] = y0;
    out4[i0 + 1] = y1;
}

extern "C" void kernel_launch(void* const* d_in, const int* in_sizes, int n_in,
                              void* d_out, int out_size) {
    const float* input  = (const float*)d_in[0];   // [B, N] fp32
    const float* weight = (const float*)d_in[1];   // [N, N] fp32
    const float* bias   = (const float*)d_in[2];   // [N]    fp32
    float* out = (float*)d_out;

    // 1) Extract diagonal into device scratch.
    extract_diag_kernel<<<(N_DIM + 255) / 256, 256>>>(weight);

    // 2) Fused elementwise scale + bias, 8 floats/thread (2x float4, MLP=2).
    const unsigned total8 = (unsigned)B_DIM * N_DIM / 8;   // 4194304
    const unsigned threads = 256;
    const unsigned blocks = total8 / threads;              // 16384, exact
    scale_bias_kernel<<<blocks, threads>>>(
        reinterpret_cast<const float4*>(input),
        reinterpret_cast<const float4*>(bias),
        reinterpret_cast<float4*>(out));
}